// round 2
// baseline (speedup 1.0000x reference)
#include <cuda_runtime.h>
#include <cstdint>

#define NVOX 400000
#define NPTS 800000

// ---------------- scratch (device globals; no allocation allowed) ----------
__device__ float g_red [(size_t)NVOX * 64];        // 102.4 MB
__device__ float g_ssum[(size_t)4 * NVOX * 64];    // 409.6 MB
__device__ float g_cnt [(size_t)4 * NVOX];         // 6.4 MB
__device__ float g_att [(size_t)4 * NVOX * 32];    // 204.8 MB
__device__ float g_proj[(size_t)NVOX * 64];        // 102.4 MB
__device__ float g_Wc  [32 * 64];                  // W_out @ W_lin1[64:128]

__device__ __forceinline__ float sigm(float x) { return 1.f / (1.f + __expf(-x)); }

__device__ __forceinline__ void amaxf(float* a, float v) {
    if (v > 0.f) atomicMax((int*)a, __float_as_int(v));
    else         atomicMin((unsigned int*)a, __float_as_uint(v));
}

__device__ __forceinline__ void red4(float* p, float a, float b, float c, float d) {
    asm volatile("red.global.add.v4.f32 [%0], {%1,%2,%3,%4};"
                 :: "l"(p), "f"(a), "f"(b), "f"(c), "f"(d) : "memory");
}

// ---------------- init kernels ---------------------------------------------
__global__ void k_zero_scratch() {
    const size_t NS = (size_t)4 * NVOX * 64 / 4;   // float4 count of g_ssum
    const size_t NC = (size_t)4 * NVOX / 4;        // float4 count of g_cnt
    size_t i = (size_t)blockIdx.x * blockDim.x + threadIdx.x;
    float4 z = make_float4(0.f, 0.f, 0.f, 0.f);
    if (i < NS)            ((float4*)g_ssum)[i]      = z;
    else if (i < NS + NC)  ((float4*)g_cnt)[i - NS]  = z;
}

__global__ void k_fill_out(float* __restrict__ out, int n) {
    int i = blockIdx.x * blockDim.x + threadIdx.x;
    if (i < n) ((unsigned int*)out)[i] = 0xFF800000u;   // -inf
}

// Wc[k][c] = sum_t W_out[k][t] * W_lin1[64+t][c]   (fused enters W_lin1 linearly)
__global__ void k_wc(const float* __restrict__ Wout, const float* __restrict__ W1) {
    int idx = blockIdx.x * blockDim.x + threadIdx.x;   // 2048 = 32*64
    if (idx >= 32 * 64) return;
    int k = idx >> 6, c = idx & 63;
    float s = 0.f;
    for (int t = 0; t < 64; t++) s += Wout[k * 64 + t] * W1[(64 + t) * 64 + c];
    g_Wc[idx] = s;
}

// ---------------- K1: red = relu(x @ W_red + b); scatter-add to 4 scales ---
__global__ __launch_bounds__(128) void k_red(
    const float* __restrict__ x, const float* __restrict__ W,
    const float* __restrict__ b,
    const int* __restrict__ i0, const int* __restrict__ i1,
    const int* __restrict__ i2, const int* __restrict__ i3)
{
    __shared__ float4 Ws[64 * 16];                 // W_red [64][64] as float4 rows
    int tid = threadIdx.x;
    for (int i = tid; i < 64 * 16; i += 128) Ws[i] = ((const float4*)W)[i];
    __syncthreads();

    int v = blockIdx.x * 128 + tid;
    if (v >= NVOX) return;
    const float4* xr = (const float4*)(x + (size_t)v * 64);

    float acc[64];
#pragma unroll
    for (int c = 0; c < 64; c++) acc[c] = 0.f;

#pragma unroll
    for (int kq = 0; kq < 16; kq++) {
        float4 x4 = __ldg(xr + kq);
        float xv[4] = {x4.x, x4.y, x4.z, x4.w};
#pragma unroll
        for (int kk = 0; kk < 4; kk++) {
            int k = kq * 4 + kk;
#pragma unroll
            for (int c4 = 0; c4 < 16; c4++) {
                float4 w = Ws[k * 16 + c4];
                acc[c4 * 4 + 0] += xv[kk] * w.x;
                acc[c4 * 4 + 1] += xv[kk] * w.y;
                acc[c4 * 4 + 2] += xv[kk] * w.z;
                acc[c4 * 4 + 3] += xv[kk] * w.w;
            }
        }
    }
#pragma unroll
    for (int c = 0; c < 64; c++) acc[c] = fmaxf(acc[c] + __ldg(b + c), 0.f);

    float4* rr = (float4*)(g_red + (size_t)v * 64);
#pragma unroll
    for (int q = 0; q < 16; q++)
        rr[q] = make_float4(acc[4 * q], acc[4 * q + 1], acc[4 * q + 2], acc[4 * q + 3]);

    const int* invs[4] = {i0, i1, i2, i3};
#pragma unroll
    for (int j = 0; j < 4; j++) {
        int s = __ldg(invs[j] + v);
        float* dst = g_ssum + ((size_t)j * NVOX + s) * 64;
#pragma unroll
        for (int q = 0; q < 16; q++)
            red4(dst + q * 4, acc[4 * q], acc[4 * q + 1], acc[4 * q + 2], acc[4 * q + 3]);
        atomicAdd(g_cnt + (size_t)j * NVOX + s, 1.0f);
    }
}

// ---------------- K2: per live segment: relu((ssum/cnt) @ W_att[j] + b) ----
__global__ __launch_bounds__(256) void k_scale(
    const float* __restrict__ Watt, const float* __restrict__ batt)
{
    __shared__ float4 Ws[64 * 8];   // W_att[j] [64][32]
    __shared__ float  bs[32];
    int j = blockIdx.y;
    int tid = threadIdx.x;
    for (int i = tid; i < 64 * 8; i += 256)
        Ws[i] = ((const float4*)(Watt + (size_t)j * 64 * 32))[i];
    if (tid < 32) bs[tid] = batt[j * 32 + tid];
    __syncthreads();

    int s = blockIdx.x * 256 + tid;
    if (s >= NVOX) return;
    float c = g_cnt[(size_t)j * NVOX + s];
    if (c == 0.f) return;                       // dead segment: never gathered
    float invc = 1.f / c;

    const float4* xr = (const float4*)(g_ssum + ((size_t)j * NVOX + s) * 64);
    float acc[32];
#pragma unroll
    for (int i = 0; i < 32; i++) acc[i] = 0.f;

#pragma unroll
    for (int kq = 0; kq < 16; kq++) {
        float4 x4 = __ldg(xr + kq);
        float xv[4] = {x4.x * invc, x4.y * invc, x4.z * invc, x4.w * invc};
#pragma unroll
        for (int kk = 0; kk < 4; kk++) {
#pragma unroll
            for (int c4 = 0; c4 < 8; c4++) {
                float4 w = Ws[(kq * 4 + kk) * 8 + c4];
                acc[c4 * 4 + 0] += xv[kk] * w.x;
                acc[c4 * 4 + 1] += xv[kk] * w.y;
                acc[c4 * 4 + 2] += xv[kk] * w.z;
                acc[c4 * 4 + 3] += xv[kk] * w.w;
            }
        }
    }
    float4* orow = (float4*)(g_att + ((size_t)j * NVOX + s) * 32);
#pragma unroll
    for (int q = 0; q < 8; q++) {
        float4 o;
        o.x = fmaxf(acc[4 * q + 0] + bs[4 * q + 0], 0.f);
        o.y = fmaxf(acc[4 * q + 1] + bs[4 * q + 1], 0.f);
        o.z = fmaxf(acc[4 * q + 2] + bs[4 * q + 2], 0.f);
        o.w = fmaxf(acc[4 * q + 3] + bs[4 * q + 3], 0.f);
        orow[q] = o;
    }
}

// ---------------- K3: fusion + attention + MLP per voxel -> proj -----------
__global__ __launch_bounds__(128, 3) void k_fuse(
    const float* __restrict__ Wfc,  const float* __restrict__ Wfcs,
    const float* __restrict__ bfcs, const float* __restrict__ W1,
    const float* __restrict__ W2,   const float* __restrict__ b2,
    const int* __restrict__ i0, const int* __restrict__ i1,
    const int* __restrict__ i2, const int* __restrict__ i3)
{
    __shared__ float4 sWfc [32 * 8];        // 4 KB
    __shared__ float4 sWfcs[4 * 32 * 8];    // 16 KB
    __shared__ float  sbfcs[4 * 32];
    __shared__ float4 sWc  [32 * 16];       // 8 KB
    __shared__ float4 sW2  [64 * 16];       // 16 KB
    __shared__ float  sb2  [64];

    int tid = threadIdx.x;
    for (int i = tid; i < 32 * 8;     i += 128) sWfc[i]  = ((const float4*)Wfc)[i];
    for (int i = tid; i < 4 * 32 * 8; i += 128) sWfcs[i] = ((const float4*)Wfcs)[i];
    for (int i = tid; i < 32 * 16;    i += 128) sWc[i]   = ((const float4*)g_Wc)[i];
    for (int i = tid; i < 64 * 16;    i += 128) sW2[i]   = ((const float4*)W2)[i];
    if (tid < 64)  sb2[tid]  = b2[tid];
    if (tid < 128) sbfcs[tid] = bfcs[tid];
    __syncthreads();

    int v = blockIdx.x * 128 + tid;
    if (v >= NVOX) return;
    int sg[4] = {__ldg(i0 + v), __ldg(i1 + v), __ldg(i2 + v), __ldg(i3 + v)};

    // feat_S = sum_j s_j  (gather pass 1)
    float fS[32];
#pragma unroll
    for (int i = 0; i < 32; i++) fS[i] = 0.f;
#pragma unroll
    for (int j = 0; j < 4; j++) {
        const float4* sp = (const float4*)(g_att + ((size_t)j * NVOX + sg[j]) * 32);
#pragma unroll
        for (int q = 0; q < 8; q++) {
            float4 s4 = __ldg(sp + q);
            fS[4 * q + 0] += s4.x; fS[4 * q + 1] += s4.y;
            fS[4 * q + 2] += s4.z; fS[4 * q + 3] += s4.w;
        }
    }

    // feat_Z = relu(feat_S @ W_fc)
    float fZ[32];
#pragma unroll
    for (int i = 0; i < 32; i++) fZ[i] = 0.f;
#pragma unroll
    for (int k = 0; k < 32; k++) {
        float xv = fS[k];
#pragma unroll
        for (int c4 = 0; c4 < 8; c4++) {
            float4 w = sWfc[k * 8 + c4];
            fZ[c4 * 4 + 0] += xv * w.x; fZ[c4 * 4 + 1] += xv * w.y;
            fZ[c4 * 4 + 2] += xv * w.z; fZ[c4 * 4 + 3] += xv * w.w;
        }
    }
#pragma unroll
    for (int i = 0; i < 32; i++) fZ[i] = fmaxf(fZ[i], 0.f);

    // m = sum_j s_j * sigmoid(feat_Z @ W_fcs[j] + b_fcs[j])   (gather pass 2, L1-warm)
    float m[32];
#pragma unroll
    for (int i = 0; i < 32; i++) m[i] = 0.f;
#pragma unroll
    for (int j = 0; j < 4; j++) {
        const float4* sp = (const float4*)(g_att + ((size_t)j * NVOX + sg[j]) * 32);
#pragma unroll
        for (int c4 = 0; c4 < 8; c4++) {
            float4 a = make_float4(sbfcs[j * 32 + 4 * c4 + 0], sbfcs[j * 32 + 4 * c4 + 1],
                                   sbfcs[j * 32 + 4 * c4 + 2], sbfcs[j * 32 + 4 * c4 + 3]);
#pragma unroll
            for (int k = 0; k < 32; k++) {
                float4 w = sWfcs[(j * 32 + k) * 8 + c4];
                a.x += fZ[k] * w.x; a.y += fZ[k] * w.y;
                a.z += fZ[k] * w.z; a.w += fZ[k] * w.w;
            }
            float4 s4 = __ldg(sp + c4);
            m[4 * c4 + 0] += s4.x * sigm(a.x);
            m[4 * c4 + 1] += s4.y * sigm(a.y);
            m[4 * c4 + 2] += s4.z * sigm(a.z);
            m[4 * c4 + 3] += s4.w * sigm(a.w);
        }
    }

    // h = relu(red @ W1[0:64] + m @ Wc)
    float h[64];
#pragma unroll
    for (int i = 0; i < 64; i++) h[i] = 0.f;
#pragma unroll
    for (int k = 0; k < 32; k++) {
        float xv = m[k];
#pragma unroll
        for (int c4 = 0; c4 < 16; c4++) {
            float4 w = sWc[k * 16 + c4];
            h[c4 * 4 + 0] += xv * w.x; h[c4 * 4 + 1] += xv * w.y;
            h[c4 * 4 + 2] += xv * w.z; h[c4 * 4 + 3] += xv * w.w;
        }
    }
    const float4* rp  = (const float4*)(g_red + (size_t)v * 64);
    const float4* W1p = (const float4*)W1;     // rows 0..63 (red part)
#pragma unroll
    for (int kq = 0; kq < 16; kq++) {
        float4 r4 = __ldg(rp + kq);
        float xv[4] = {r4.x, r4.y, r4.z, r4.w};
#pragma unroll
        for (int kk = 0; kk < 4; kk++) {
            int k = kq * 4 + kk;
#pragma unroll
            for (int c4 = 0; c4 < 16; c4++) {
                float4 w = __ldg(W1p + k * 16 + c4);
                h[c4 * 4 + 0] += xv[kk] * w.x; h[c4 * 4 + 1] += xv[kk] * w.y;
                h[c4 * 4 + 2] += xv[kk] * w.z; h[c4 * 4 + 3] += xv[kk] * w.w;
            }
        }
    }
#pragma unroll
    for (int i = 0; i < 64; i++) h[i] = fmaxf(h[i], 0.f);

    // proj = h @ W_lin2 + b_lin2
    float p[64];
#pragma unroll
    for (int i = 0; i < 64; i++) p[i] = sb2[i];
#pragma unroll
    for (int k = 0; k < 64; k++) {
        float xv = h[k];
#pragma unroll
        for (int c4 = 0; c4 < 16; c4++) {
            float4 w = sW2[k * 16 + c4];
            p[c4 * 4 + 0] += xv * w.x; p[c4 * 4 + 1] += xv * w.y;
            p[c4 * 4 + 2] += xv * w.z; p[c4 * 4 + 3] += xv * w.w;
        }
    }
    float4* pr = (float4*)(g_proj + (size_t)v * 64);
#pragma unroll
    for (int q = 0; q < 16; q++)
        pr[q] = make_float4(p[4 * q], p[4 * q + 1], p[4 * q + 2], p[4 * q + 3]);
}

// ---------------- K4: gather proj to points, segment-max to out ------------
__global__ __launch_bounds__(256) void k_points(
    const int* __restrict__ invp, const int* __restrict__ invo,
    float* __restrict__ out)
{
    int t = blockIdx.x * 256 + threadIdx.x;
    int pidx = t >> 4, q = t & 15;
    if (pidx >= NPTS) return;
    int r = __ldg(invp + pidx);
    int o = __ldg(invo + pidx);
    float4 v = __ldg((const float4*)(g_proj + (size_t)r * 64) + q);
    float* ob = out + (size_t)o * 64 + q * 4;
    amaxf(ob + 0, v.x); amaxf(ob + 1, v.y);
    amaxf(ob + 2, v.z); amaxf(ob + 3, v.w);
}

// ---------------- launch ----------------------------------------------------
// Inputs are identified by ELEMENT COUNT + first-appearance order (dict order
// of setup_inputs), robust to whether scalar n0..n3/n_out entries appear:
//   400000 x4  -> inv0..inv3
//   800000 x2  -> inv_pts, inv_out
//   25600000   -> input_data
//   4096  x3   -> W_red, W_fcs, W_lin2   (dict order)
//   8192  x2   -> W_att, W_lin1
//   64    x2   -> b_red, b_lin2
//   128   x2   -> b_att, b_fcs
//   1024       -> W_fc
//   2048       -> W_out
extern "C" void kernel_launch(void* const* d_in, const int* in_sizes, int n_in,
                              void* d_out, int out_size)
{
    const float *x = 0, *Wred = 0, *bred = 0, *Watt = 0, *batt = 0;
    const float *Wfcs = 0, *bfcs = 0, *Wfc = 0, *Wout = 0, *W1 = 0, *W2 = 0, *b2 = 0;
    const int *i0 = 0, *i1 = 0, *i2 = 0, *i3 = 0, *invp = 0, *invo = 0;

    int c400k = 0, c800k = 0, c4096 = 0, c8192 = 0, c64 = 0, c128 = 0;
    for (int i = 0; i < n_in; i++) {
        int s = in_sizes[i];
        const void* p = d_in[i];
        switch (s) {
            case 400000:
                if      (c400k == 0) i0 = (const int*)p;
                else if (c400k == 1) i1 = (const int*)p;
                else if (c400k == 2) i2 = (const int*)p;
                else                 i3 = (const int*)p;
                c400k++; break;
            case 800000:
                if (c800k == 0) invp = (const int*)p; else invo = (const int*)p;
                c800k++; break;
            case 25600000: x = (const float*)p; break;
            case 4096:
                if      (c4096 == 0) Wred = (const float*)p;
                else if (c4096 == 1) Wfcs = (const float*)p;
                else                 W2   = (const float*)p;
                c4096++; break;
            case 8192:
                if (c8192 == 0) Watt = (const float*)p; else W1 = (const float*)p;
                c8192++; break;
            case 64:
                if (c64 == 0) bred = (const float*)p; else b2 = (const float*)p;
                c64++; break;
            case 128:
                if (c128 == 0) batt = (const float*)p; else bfcs = (const float*)p;
                c128++; break;
            case 1024: Wfc  = (const float*)p; break;
            case 2048: Wout = (const float*)p; break;
            default: break;   // size-1 scalars (n0..n3, n_out) ignored
        }
    }

    float* out = (float*)d_out;

    k_fill_out<<<(out_size + 255) / 256, 256>>>(out, out_size);

    const size_t NZ4 = (size_t)4 * NVOX * 64 / 4 + (size_t)4 * NVOX / 4;
    k_zero_scratch<<<(unsigned)((NZ4 + 255) / 256), 256>>>();

    k_wc<<<8, 256>>>(Wout, W1);

    k_red<<<(NVOX + 127) / 128, 128>>>(x, Wred, bred, i0, i1, i2, i3);

    k_scale<<<dim3((NVOX + 255) / 256, 4), 256>>>(Watt, batt);

    k_fuse<<<(NVOX + 127) / 128, 128>>>(Wfc, Wfcs, bfcs, W1, W2, b2, i0, i1, i2, i3);

    k_points<<<((size_t)NPTS * 16 + 255) / 256, 256>>>(invp, invo, out);
}